// round 1
// baseline (speedup 1.0000x reference)
#include <cuda_runtime.h>
#include <math.h>

#define BB 4
#define TT 4096
#define CC 512
#define HD 64

// scratch for projected q/k/v  (B*T*H floats each = 4 MB)
__device__ float g_q[BB * TT * HD];
__device__ float g_k[BB * TT * HD];
__device__ float g_v[BB * TT * HD];

// ---------------------------------------------------------------------------
// Projection: out[r][h] = sum_k x[r][k] * W[k][h], rows = B*T = 16384
// grid: (256, 1, 3), block: 256 threads, 64x64 tile, 4x4 microtile
// ---------------------------------------------------------------------------
__global__ void proj_kernel(const float* __restrict__ x,
                            const float* __restrict__ Wk,
                            const float* __restrict__ Wq,
                            const float* __restrict__ Wv) {
    __shared__ float xs[64][33];
    __shared__ float ws[32][65];

    const float* W;
    float* out;
    if (blockIdx.z == 0)      { W = Wk; out = g_k; }
    else if (blockIdx.z == 1) { W = Wq; out = g_q; }
    else                      { W = Wv; out = g_v; }

    const int row0 = blockIdx.x * 64;
    const int tid = threadIdx.x;
    const int ty = tid >> 4;       // 0..15
    const int tx = tid & 15;       // 0..15

    float acc[4][4];
#pragma unroll
    for (int i = 0; i < 4; i++)
#pragma unroll
        for (int m = 0; m < 4; m++) acc[i][m] = 0.f;

    for (int k0 = 0; k0 < CC; k0 += 32) {
        // load x tile [64 x 32]
#pragma unroll
        for (int idx = tid; idx < 64 * 32; idx += 256) {
            int r = idx >> 5, c = idx & 31;
            xs[r][c] = x[(size_t)(row0 + r) * CC + (k0 + c)];
        }
        // load W chunk [32 x 64]
#pragma unroll
        for (int idx = tid; idx < 32 * 64; idx += 256) {
            int r = idx >> 6, c = idx & 63;
            ws[r][c] = W[(size_t)(k0 + r) * HD + c];
        }
        __syncthreads();

#pragma unroll 8
        for (int k = 0; k < 32; k++) {
            float a[4], b[4];
#pragma unroll
            for (int i = 0; i < 4; i++) a[i] = xs[ty + 16 * i][k];
#pragma unroll
            for (int m = 0; m < 4; m++) b[m] = ws[k][tx + 16 * m];
#pragma unroll
            for (int i = 0; i < 4; i++)
#pragma unroll
                for (int m = 0; m < 4; m++) acc[i][m] += a[i] * b[m];
        }
        __syncthreads();
    }

#pragma unroll
    for (int i = 0; i < 4; i++)
#pragma unroll
        for (int m = 0; m < 4; m++)
            out[(size_t)(row0 + ty + 16 * i) * HD + (tx + 16 * m)] = acc[i][m];
}

// ---------------------------------------------------------------------------
// Flash attention (causal, online softmax). BLOCK_M = BLOCK_N = 64, H = 64.
// grid: (T/64, B), block: 256 threads = 16x16, 4x4 microtiles.
// smem: Qs, Ks, Vs, Ps each [64][65] floats -> 66560 bytes dynamic.
// ---------------------------------------------------------------------------
__global__ void flash_kernel(float* __restrict__ out) {
    extern __shared__ float smem[];
    float (*Qs)[65] = (float(*)[65])(smem);
    float (*Ks)[65] = (float(*)[65])(smem + 64 * 65);
    float (*Vs)[65] = (float(*)[65])(smem + 2 * 64 * 65);
    float (*Ps)[65] = (float(*)[65])(smem + 3 * 64 * 65);

    const int b  = blockIdx.y;
    const int qb = blockIdx.x;
    const int tid = threadIdx.x;
    const int ty = tid >> 4;
    const int tx = tid & 15;

    const float scale = rsqrtf((float)CC);   // reference scales by C**-0.5

    const float* Qg = g_q + ((size_t)b * TT + (size_t)qb * 64) * HD;

    // load Q tile, pre-scaled
#pragma unroll
    for (int idx = tid; idx < 64 * 64; idx += 256) {
        int r = idx >> 6, c = idx & 63;
        Qs[r][c] = Qg[(size_t)r * HD + c] * scale;
    }

    float m_i[4], l_i[4], acc[4][4];
#pragma unroll
    for (int i = 0; i < 4; i++) {
        m_i[i] = -INFINITY;
        l_i[i] = 0.f;
#pragma unroll
        for (int m = 0; m < 4; m++) acc[i][m] = 0.f;
    }

    for (int jb = 0; jb <= qb; jb++) {
        const float* Kg = g_k + ((size_t)b * TT + (size_t)jb * 64) * HD;
        const float* Vg = g_v + ((size_t)b * TT + (size_t)jb * 64) * HD;

        __syncthreads();   // all prior-iteration smem reads done
#pragma unroll
        for (int idx = tid; idx < 64 * 64; idx += 256) {
            int r = idx >> 6, c = idx & 63;
            Ks[r][c] = Kg[(size_t)r * HD + c];
            Vs[r][c] = Vg[(size_t)r * HD + c];
        }
        __syncthreads();

        // ---- S = Q K^T  (thread rows: ty+16i, kv cols: tx+16j) ----
        float s[4][4];
#pragma unroll
        for (int i = 0; i < 4; i++)
#pragma unroll
            for (int j = 0; j < 4; j++) s[i][j] = 0.f;

#pragma unroll 8
        for (int h = 0; h < 64; h++) {
            float a[4], bb[4];
#pragma unroll
            for (int i = 0; i < 4; i++) a[i] = Qs[ty + 16 * i][h];
#pragma unroll
            for (int j = 0; j < 4; j++) bb[j] = Ks[tx + 16 * j][h];
#pragma unroll
            for (int i = 0; i < 4; i++)
#pragma unroll
                for (int j = 0; j < 4; j++) s[i][j] += a[i] * bb[j];
        }

        // causal mask on the diagonal block
        if (jb == qb) {
#pragma unroll
            for (int i = 0; i < 4; i++)
#pragma unroll
                for (int j = 0; j < 4; j++)
                    if (tx + 16 * j > ty + 16 * i) s[i][j] = -INFINITY;
        }

        // ---- row max over 64 kv cols (4 local + shuffle over 16 lanes) ----
        float mnew[4];
#pragma unroll
        for (int i = 0; i < 4; i++) {
            float v = fmaxf(fmaxf(s[i][0], s[i][1]), fmaxf(s[i][2], s[i][3]));
            mnew[i] = v;
        }
#pragma unroll
        for (int off = 8; off >= 1; off >>= 1)
#pragma unroll
            for (int i = 0; i < 4; i++)
                mnew[i] = fmaxf(mnew[i], __shfl_xor_sync(0xffffffffu, mnew[i], off, 16));

        float alpha[4];
#pragma unroll
        for (int i = 0; i < 4; i++) {
            float mn = fmaxf(m_i[i], mnew[i]);
            alpha[i] = __expf(m_i[i] - mn);
            m_i[i] = mn;
        }

        // ---- p = exp(s - m), row sum ----
        float rowsum[4];
#pragma unroll
        for (int i = 0; i < 4; i++) {
            float rs = 0.f;
#pragma unroll
            for (int j = 0; j < 4; j++) {
                float p = __expf(s[i][j] - m_i[i]);
                s[i][j] = p;
                rs += p;
            }
            rowsum[i] = rs;
        }
#pragma unroll
        for (int off = 8; off >= 1; off >>= 1)
#pragma unroll
            for (int i = 0; i < 4; i++)
                rowsum[i] += __shfl_xor_sync(0xffffffffu, rowsum[i], off, 16);

#pragma unroll
        for (int i = 0; i < 4; i++) {
            l_i[i] = l_i[i] * alpha[i] + rowsum[i];
#pragma unroll
            for (int m = 0; m < 4; m++) acc[i][m] *= alpha[i];
        }

        // ---- stage P to smem, then O += P V ----
#pragma unroll
        for (int i = 0; i < 4; i++)
#pragma unroll
            for (int j = 0; j < 4; j++)
                Ps[ty + 16 * i][tx + 16 * j] = s[i][j];
        __syncthreads();

#pragma unroll 8
        for (int j = 0; j < 64; j++) {
            float p4[4], v4[4];
#pragma unroll
            for (int i = 0; i < 4; i++) p4[i] = Ps[ty + 16 * i][j];
#pragma unroll
            for (int m = 0; m < 4; m++) v4[m] = Vs[j][tx + 16 * m];
#pragma unroll
            for (int i = 0; i < 4; i++)
#pragma unroll
                for (int m = 0; m < 4; m++) acc[i][m] += p4[i] * v4[m];
        }
    }

    // epilogue: O / l
#pragma unroll
    for (int i = 0; i < 4; i++) {
        float inv = 1.0f / l_i[i];
        size_t row = (size_t)b * TT + (size_t)qb * 64 + (ty + 16 * i);
#pragma unroll
        for (int m = 0; m < 4; m++)
            out[row * HD + (tx + 16 * m)] = acc[i][m] * inv;
    }
}

// ---------------------------------------------------------------------------
extern "C" void kernel_launch(void* const* d_in, const int* in_sizes, int n_in,
                              void* d_out, int out_size) {
    const float* x  = (const float*)d_in[0];
    const float* Wk = (const float*)d_in[1];
    const float* Wq = (const float*)d_in[2];
    const float* Wv = (const float*)d_in[3];
    float* out = (float*)d_out;

    (void)in_sizes; (void)n_in; (void)out_size;

    // projections: 16384 rows / 64 per block = 256 blocks, z = {k,q,v}
    dim3 pgrid(256, 1, 3);
    proj_kernel<<<pgrid, 256>>>(x, Wk, Wq, Wv);

    // flash attention
    const int smem_bytes = 4 * 64 * 65 * (int)sizeof(float);  // 66560
    static int attr_set = 0;
    if (!attr_set) {
        cudaFuncSetAttribute(flash_kernel,
                             cudaFuncAttributeMaxDynamicSharedMemorySize,
                             smem_bytes);
        attr_set = 1;
    }
    dim3 fgrid(TT / 64, BB);
    flash_kernel<<<fgrid, 256, smem_bytes>>>(out);
}

// round 2
// speedup vs baseline: 1.5859x; 1.5859x over previous
#include <cuda_runtime.h>
#include <math.h>

#define BB 4
#define TT 4096
#define CC 512
#define HD 64

#define BM 64            // q-tile rows
#define BN 64            // kv-tile rows
#define SPLIT 16         // max KV tiles per CTA
#define NITEMS_PER_B 160 // sum_{qb=0..63} ceil((qb+1)/16) = 16*(1+2+3+4)
#define NITEMS (BB * NITEMS_PER_B)   // 640
#define PAD 68           // row stride (floats) for smem tiles

// projected q/k/v scratch (4 MB each)
__device__ float g_q[BB * TT * HD];
__device__ float g_k[BB * TT * HD];
__device__ float g_v[BB * TT * HD];

// split-KV partials: per (b, qb, split<=4): acc [64][64], m[64], l[64]
__device__ float g_pacc[BB * 64 * 4 * BM * HD];   // 16.7 MB
__device__ float g_pm[BB * 64 * 4 * BM];
__device__ float g_pl[BB * 64 * 4 * BM];

// ---------------------------------------------------------------------------
// Projection GEMM: out[r][h] = sum_k x[r][k] * W[k][h]; rows = B*T = 16384
// 64x64 tile, 256 threads, thread = 4 consecutive rows x 4 consecutive cols.
// ---------------------------------------------------------------------------
__global__ __launch_bounds__(256) void proj_kernel(const float* __restrict__ x,
                                                   const float* __restrict__ Wk,
                                                   const float* __restrict__ Wq,
                                                   const float* __restrict__ Wv) {
    __shared__ float xs_t[32][PAD];   // [k][row]  (transposed)
    __shared__ float ws[32][PAD];     // [k][col]

    const float* W;
    float* out;
    if (blockIdx.z == 0)      { W = Wk; out = g_k; }
    else if (blockIdx.z == 1) { W = Wq; out = g_q; }
    else                      { W = Wv; out = g_v; }

    const int row0 = blockIdx.x * 64;
    const int tid = threadIdx.x;
    const int ty = tid >> 4;   // 0..15 -> rows ty*4..ty*4+3
    const int tx = tid & 15;   // 0..15 -> cols tx*4..tx*4+3

    float acc[4][4];
#pragma unroll
    for (int i = 0; i < 4; i++)
#pragma unroll
        for (int m = 0; m < 4; m++) acc[i][m] = 0.f;

    for (int k0 = 0; k0 < CC; k0 += 32) {
        __syncthreads();
        // x tile [64 rows x 32 k] -> xs_t[k][row]; 512 float4 reads
#pragma unroll
        for (int it = 0; it < 2; it++) {
            int f = tid + it * 256;
            int r = f >> 3, c4 = (f & 7) << 2;
            float4 v = *(const float4*)&x[(size_t)(row0 + r) * CC + k0 + c4];
            xs_t[c4 + 0][r] = v.x;
            xs_t[c4 + 1][r] = v.y;
            xs_t[c4 + 2][r] = v.z;
            xs_t[c4 + 3][r] = v.w;
        }
        // W chunk [32 k x 64 cols] -> ws[k][col]; 512 float4
#pragma unroll
        for (int it = 0; it < 2; it++) {
            int f = tid + it * 256;
            int r = f >> 4, c4 = (f & 15) << 2;
            *(float4*)&ws[r][c4] = *(const float4*)&W[(size_t)(k0 + r) * HD + c4];
        }
        __syncthreads();

#pragma unroll
        for (int k = 0; k < 32; k++) {
            float4 a = *(const float4*)&xs_t[k][ty * 4];
            float4 b = *(const float4*)&ws[k][tx * 4];
            float av[4] = {a.x, a.y, a.z, a.w};
            float bv[4] = {b.x, b.y, b.z, b.w};
#pragma unroll
            for (int i = 0; i < 4; i++)
#pragma unroll
                for (int m = 0; m < 4; m++) acc[i][m] += av[i] * bv[m];
        }
    }

#pragma unroll
    for (int i = 0; i < 4; i++)
        *(float4*)&out[(size_t)(row0 + ty * 4 + i) * HD + tx * 4] =
            make_float4(acc[i][0], acc[i][1], acc[i][2], acc[i][3]);
}

// ---------------------------------------------------------------------------
// Flash attention with split-KV. Each work item = (b, qb, split) processes at
// most SPLIT KV tiles and writes unnormalized partial (acc, m, l).
// ---------------------------------------------------------------------------
__global__ __launch_bounds__(256, 3) void flash_kernel() {
    extern __shared__ float smem[];
    float (*Qs_t)[PAD] = (float(*)[PAD])(smem);                 // [h][row]
    float (*Ks_t)[PAD] = (float(*)[PAD])(smem + 64 * PAD);      // [h][col]
    float (*Vs)[PAD]   = (float(*)[PAD])(smem + 2 * 64 * PAD);  // [j][hcol]
    float (*Ps_t)[PAD] = (float(*)[PAD])(smem + 3 * 64 * PAD);  // [j][row]

    // decode work item
    const int item = blockIdx.x;
    const int b = item / NITEMS_PER_B;
    const int r = item - b * NITEMS_PER_B;
    int qb, sp;
    if (r < 16)      { qb = r;                sp = 0; }
    else if (r < 48) { qb = 16 + (r - 16) / 2; sp = (r - 16) % 2; }
    else if (r < 96) { qb = 32 + (r - 48) / 3; sp = (r - 48) % 3; }
    else             { qb = 48 + (r - 96) / 4; sp = (r - 96) % 4; }

    const int jb_lo = sp * SPLIT;
    const int jb_hi = min(jb_lo + SPLIT, qb + 1);   // exclusive

    const int tid = threadIdx.x;
    const int ty = tid >> 4;
    const int tx = tid & 15;

    const float scale = rsqrtf((float)CC);

    const float* Qg = g_q + ((size_t)b * TT + (size_t)qb * BM) * HD;

    // load Q tile transposed + pre-scaled: Qs_t[h][row]
#pragma unroll
    for (int it = 0; it < 4; it++) {
        int f = tid + it * 256;            // 1024 float4s
        int row = f >> 4, c4 = (f & 15) << 2;
        float4 v = *(const float4*)&Qg[(size_t)row * HD + c4];
        Qs_t[c4 + 0][row] = v.x * scale;
        Qs_t[c4 + 1][row] = v.y * scale;
        Qs_t[c4 + 2][row] = v.z * scale;
        Qs_t[c4 + 3][row] = v.w * scale;
    }

    float m_i[4], l_i[4], acc[4][4];
#pragma unroll
    for (int i = 0; i < 4; i++) {
        m_i[i] = -INFINITY;
        l_i[i] = 0.f;
#pragma unroll
        for (int m = 0; m < 4; m++) acc[i][m] = 0.f;
    }

    for (int jb = jb_lo; jb < jb_hi; jb++) {
        const float* Kg = g_k + ((size_t)b * TT + (size_t)jb * BN) * HD;
        const float* Vg = g_v + ((size_t)b * TT + (size_t)jb * BN) * HD;

        __syncthreads();   // previous PV reads of Vs/Ps done; Qs load visible
        // K transposed, V row-major
#pragma unroll
        for (int it = 0; it < 4; it++) {
            int f = tid + it * 256;
            int row = f >> 4, c4 = (f & 15) << 2;
            float4 kv = *(const float4*)&Kg[(size_t)row * HD + c4];
            Ks_t[c4 + 0][row] = kv.x;
            Ks_t[c4 + 1][row] = kv.y;
            Ks_t[c4 + 2][row] = kv.z;
            Ks_t[c4 + 3][row] = kv.w;
            *(float4*)&Vs[row][c4] = *(const float4*)&Vg[(size_t)row * HD + c4];
        }
        __syncthreads();

        // ---- S = Q K^T : rows ty*4+i, cols tx*4+j ----
        float s[4][4];
#pragma unroll
        for (int i = 0; i < 4; i++)
#pragma unroll
            for (int j = 0; j < 4; j++) s[i][j] = 0.f;

#pragma unroll 16
        for (int h = 0; h < 64; h++) {
            float4 a = *(const float4*)&Qs_t[h][ty * 4];
            float4 bb = *(const float4*)&Ks_t[h][tx * 4];
            float av[4] = {a.x, a.y, a.z, a.w};
            float bv[4] = {bb.x, bb.y, bb.z, bb.w};
#pragma unroll
            for (int i = 0; i < 4; i++)
#pragma unroll
                for (int j = 0; j < 4; j++) s[i][j] += av[i] * bv[j];
        }

        if (jb == qb) {   // causal mask on diagonal tile
#pragma unroll
            for (int i = 0; i < 4; i++)
#pragma unroll
                for (int j = 0; j < 4; j++)
                    if (tx * 4 + j > ty * 4 + i) s[i][j] = -INFINITY;
        }

        // ---- online softmax ----
        float mnew[4];
#pragma unroll
        for (int i = 0; i < 4; i++)
            mnew[i] = fmaxf(fmaxf(s[i][0], s[i][1]), fmaxf(s[i][2], s[i][3]));
#pragma unroll
        for (int off = 8; off >= 1; off >>= 1)
#pragma unroll
            for (int i = 0; i < 4; i++)
                mnew[i] = fmaxf(mnew[i], __shfl_xor_sync(0xffffffffu, mnew[i], off));

        float alpha[4];
#pragma unroll
        for (int i = 0; i < 4; i++) {
            float mn = fmaxf(m_i[i], mnew[i]);
            alpha[i] = __expf(m_i[i] - mn);
            m_i[i] = mn;
        }

        float rowsum[4];
#pragma unroll
        for (int i = 0; i < 4; i++) {
            float rs = 0.f;
#pragma unroll
            for (int j = 0; j < 4; j++) {
                float p = __expf(s[i][j] - m_i[i]);
                s[i][j] = p;
                rs += p;
            }
            rowsum[i] = rs;
        }
#pragma unroll
        for (int off = 8; off >= 1; off >>= 1)
#pragma unroll
            for (int i = 0; i < 4; i++)
                rowsum[i] += __shfl_xor_sync(0xffffffffu, rowsum[i], off);

#pragma unroll
        for (int i = 0; i < 4; i++) {
            l_i[i] = l_i[i] * alpha[i] + rowsum[i];
#pragma unroll
            for (int m = 0; m < 4; m++) acc[i][m] *= alpha[i];
        }

        // stage P transposed: Ps_t[col][row]
#pragma unroll
        for (int j = 0; j < 4; j++)
            *(float4*)&Ps_t[tx * 4 + j][ty * 4] =
                make_float4(s[0][j], s[1][j], s[2][j], s[3][j]);
        __syncthreads();

        // ---- O += P V : rows ty*4+i, head cols tx*4+m ----
#pragma unroll 16
        for (int j = 0; j < 64; j++) {
            float4 p = *(const float4*)&Ps_t[j][ty * 4];
            float4 v = *(const float4*)&Vs[j][tx * 4];
            float pv[4] = {p.x, p.y, p.z, p.w};
            float vv[4] = {v.x, v.y, v.z, v.w};
#pragma unroll
            for (int i = 0; i < 4; i++)
#pragma unroll
                for (int m = 0; m < 4; m++) acc[i][m] += pv[i] * vv[m];
        }
    }

    // write partials (unnormalized)
    const int p = (b * 64 + qb) * 4 + sp;
    float* pacc = g_pacc + (size_t)p * BM * HD;
#pragma unroll
    for (int i = 0; i < 4; i++)
        *(float4*)&pacc[(ty * 4 + i) * HD + tx * 4] =
            make_float4(acc[i][0], acc[i][1], acc[i][2], acc[i][3]);
    if (tx == 0) {
#pragma unroll
        for (int i = 0; i < 4; i++) {
            g_pm[p * BM + ty * 4 + i] = m_i[i];
            g_pl[p * BM + ty * 4 + i] = l_i[i];
        }
    }
}

// ---------------------------------------------------------------------------
// Combine split partials -> final output. One CTA per (b, qb).
// ---------------------------------------------------------------------------
__global__ __launch_bounds__(256) void combine_kernel(float* __restrict__ out) {
    __shared__ float wsm[4][64];
    __shared__ float linv[64];

    const int bq = blockIdx.x;          // 0..255
    const int b = bq >> 6;
    const int qb = bq & 63;
    const int nS = qb / SPLIT + 1;
    const int tid = threadIdx.x;
    const int pbase = bq * 4;

    if (tid < 64) {
        float M = -INFINITY;
        for (int s = 0; s < nS; s++)
            M = fmaxf(M, g_pm[(pbase + s) * BM + tid]);
        float L = 0.f;
        for (int s = 0; s < nS; s++) {
            float w = __expf(g_pm[(pbase + s) * BM + tid] - M);
            wsm[s][tid] = w;
            L += g_pl[(pbase + s) * BM + tid] * w;
        }
        linv[tid] = 1.0f / L;
    }
    __syncthreads();

    float* og = out + ((size_t)b * TT + (size_t)qb * BM) * HD;
#pragma unroll
    for (int e = 0; e < 16; e++) {
        int flat = tid + e * 256;       // 0..4095
        int row = flat >> 6, c = flat & 63;
        float sum = 0.f;
        for (int s = 0; s < nS; s++)
            sum += g_pacc[(size_t)(pbase + s) * BM * HD + flat] * wsm[s][row];
        og[(size_t)row * HD + c] = sum * linv[row];
    }
}

// ---------------------------------------------------------------------------
extern "C" void kernel_launch(void* const* d_in, const int* in_sizes, int n_in,
                              void* d_out, int out_size) {
    const float* x  = (const float*)d_in[0];
    const float* Wk = (const float*)d_in[1];
    const float* Wq = (const float*)d_in[2];
    const float* Wv = (const float*)d_in[3];
    float* out = (float*)d_out;
    (void)in_sizes; (void)n_in; (void)out_size;

    dim3 pgrid(256, 1, 3);
    proj_kernel<<<pgrid, 256>>>(x, Wk, Wq, Wv);

    const int smem_bytes = 4 * 64 * PAD * (int)sizeof(float);   // 69632
    static int attr_set = 0;
    if (!attr_set) {
        cudaFuncSetAttribute(flash_kernel,
                             cudaFuncAttributeMaxDynamicSharedMemorySize,
                             smem_bytes);
        attr_set = 1;
    }
    flash_kernel<<<NITEMS, 256, smem_bytes>>>();

    combine_kernel<<<256, 256>>>(out);
}

// round 3
// speedup vs baseline: 3.4629x; 2.1835x over previous
#include <cuda_runtime.h>
#include <math.h>
#include <stdint.h>

#define BB 4
#define TT 4096
#define CC 512
#define HD 64

#define BM 128           // q-tile rows per CTA
#define BN 64            // kv-tile rows
#define SPLIT 16         // max KV tiles (of 64) per work item
#define QB_PER_B 32      // TT / BM
#define NITEMS_PER_B 80  // sum_{qb=0..31} ceil((2qb+2)/16) = 8*(1+2+3+4)
#define NITEMS (BB * NITEMS_PER_B)   // 320
#define PAD 68           // smem row stride (floats/uints)

// projected q/k/v scratch (4 MB each)
__device__ float g_q[BB * TT * HD];
__device__ float g_k[BB * TT * HD];
__device__ float g_v[BB * TT * HD];

// split-KV partials: per (b, qb, split<4): acc [128][64], m[128], l[128]
__device__ float g_pacc[BB * QB_PER_B * 4 * BM * HD];   // 16.7 MB
__device__ float g_pm[BB * QB_PER_B * 4 * BM];
__device__ float g_pl[BB * QB_PER_B * 4 * BM];

__device__ __forceinline__ uint32_t f2tf(float f) {
    uint32_t u;
    asm("cvt.rna.tf32.f32 %0, %1;" : "=r"(u) : "f"(f));
    return u;
}

__device__ __forceinline__ void mma_tf32(float& d0, float& d1, float& d2, float& d3,
                                         uint32_t a0, uint32_t a1, uint32_t a2, uint32_t a3,
                                         uint32_t b0, uint32_t b1) {
    asm volatile(
        "mma.sync.aligned.m16n8k8.row.col.f32.tf32.tf32.f32 "
        "{%0,%1,%2,%3}, {%4,%5,%6,%7}, {%8,%9}, {%0,%1,%2,%3};"
        : "+f"(d0), "+f"(d1), "+f"(d2), "+f"(d3)
        : "r"(a0), "r"(a1), "r"(a2), "r"(a3), "r"(b0), "r"(b1));
}

// ---------------------------------------------------------------------------
// Projection GEMM (unchanged from R2): out[r][h] = sum_k x[r][k] * W[k][h]
// ---------------------------------------------------------------------------
__global__ __launch_bounds__(256) void proj_kernel(const float* __restrict__ x,
                                                   const float* __restrict__ Wk,
                                                   const float* __restrict__ Wq,
                                                   const float* __restrict__ Wv) {
    __shared__ float xs_t[32][PAD];
    __shared__ float ws[32][PAD];

    const float* W;
    float* out;
    if (blockIdx.z == 0)      { W = Wk; out = g_k; }
    else if (blockIdx.z == 1) { W = Wq; out = g_q; }
    else                      { W = Wv; out = g_v; }

    const int row0 = blockIdx.x * 64;
    const int tid = threadIdx.x;
    const int ty = tid >> 4;
    const int tx = tid & 15;

    float acc[4][4];
#pragma unroll
    for (int i = 0; i < 4; i++)
#pragma unroll
        for (int m = 0; m < 4; m++) acc[i][m] = 0.f;

    for (int k0 = 0; k0 < CC; k0 += 32) {
        __syncthreads();
#pragma unroll
        for (int it = 0; it < 2; it++) {
            int f = tid + it * 256;
            int r = f >> 3, c4 = (f & 7) << 2;
            float4 v = *(const float4*)&x[(size_t)(row0 + r) * CC + k0 + c4];
            xs_t[c4 + 0][r] = v.x;
            xs_t[c4 + 1][r] = v.y;
            xs_t[c4 + 2][r] = v.z;
            xs_t[c4 + 3][r] = v.w;
        }
#pragma unroll
        for (int it = 0; it < 2; it++) {
            int f = tid + it * 256;
            int r = f >> 4, c4 = (f & 15) << 2;
            *(float4*)&ws[r][c4] = *(const float4*)&W[(size_t)(k0 + r) * HD + c4];
        }
        __syncthreads();

#pragma unroll
        for (int k = 0; k < 32; k++) {
            float4 a = *(const float4*)&xs_t[k][ty * 4];
            float4 b = *(const float4*)&ws[k][tx * 4];
            float av[4] = {a.x, a.y, a.z, a.w};
            float bv[4] = {b.x, b.y, b.z, b.w};
#pragma unroll
            for (int i = 0; i < 4; i++)
#pragma unroll
                for (int m = 0; m < 4; m++) acc[i][m] += av[i] * bv[m];
        }
    }

#pragma unroll
    for (int i = 0; i < 4; i++)
        *(float4*)&out[(size_t)(row0 + ty * 4 + i) * HD + tx * 4] =
            make_float4(acc[i][0], acc[i][1], acc[i][2], acc[i][3]);
}

// ---------------------------------------------------------------------------
// Flash attention, tensor-core (tf32 mma.sync), split-KV.
// 8 warps; warp w owns q-rows [16w, 16w+16). Q A-frags persistent in regs.
// smem (uints, tf32 bit patterns): Ks[64][PAD], Vs[64][PAD], Ps[128][PAD]
// (Ps doubles as Q staging before the mainloop).
// ---------------------------------------------------------------------------
__global__ __launch_bounds__(256, 2) void flash_kernel() {
    extern __shared__ uint32_t smem[];
    uint32_t (*Ks)[PAD] = (uint32_t(*)[PAD])(smem);
    uint32_t (*Vs)[PAD] = (uint32_t(*)[PAD])(smem + 64 * PAD);
    uint32_t (*Ps)[PAD] = (uint32_t(*)[PAD])(smem + 2 * 64 * PAD); // 128 rows

    // ---- decode work item (reversed: heavy items first) ----
    const int rr = NITEMS - 1 - blockIdx.x;
    const int b = rr / NITEMS_PER_B;
    const int r = rr - b * NITEMS_PER_B;
    int qb, sp;
    if (r < 8)       { qb = r;                 sp = 0; }
    else if (r < 24) { qb = 8 + (r - 8) / 2;   sp = (r - 8) & 1; }
    else if (r < 48) { qb = 16 + (r - 24) / 3; sp = (r - 24) % 3; }
    else             { qb = 24 + (r - 48) / 4; sp = (r - 48) & 3; }

    const int n_tiles = 2 * qb + 2;                 // causal tiles for this q-block
    const int jb_lo = sp * SPLIT;
    const int jb_hi = min(jb_lo + SPLIT, n_tiles);  // exclusive

    const int tid = threadIdx.x;
    const int w = tid >> 5;          // warp 0..7
    const int lane = tid & 31;
    const int g = lane >> 2;         // groupID 0..7
    const int c = lane & 3;          // ctig 0..3

    const float scale = rsqrtf((float)CC) * 1.44269504088896341f;  // fold log2(e)

    // ---- stage Q (scaled, tf32) into Ps, then pull A-fragments ----
    const float* Qg = g_q + ((size_t)b * TT + (size_t)qb * BM) * HD;
#pragma unroll
    for (int it = 0; it < 8; it++) {
        int f = tid + it * 256;          // 2048 float4s = 128x64
        int row = f >> 4, c4 = (f & 15) << 2;
        float4 v = *(const float4*)&Qg[(size_t)row * HD + c4];
        uint4 u = make_uint4(f2tf(v.x * scale), f2tf(v.y * scale),
                             f2tf(v.z * scale), f2tf(v.w * scale));
        *(uint4*)&Ps[row][c4] = u;
    }
    __syncthreads();

    uint32_t qf[8][4];                   // Q A-frags, kk = 0..7
#pragma unroll
    for (int kk = 0; kk < 8; kk++) {
        qf[kk][0] = Ps[16 * w + g][8 * kk + c];
        qf[kk][1] = Ps[16 * w + g + 8][8 * kk + c];
        qf[kk][2] = Ps[16 * w + g][8 * kk + c + 4];
        qf[kk][3] = Ps[16 * w + g + 8][8 * kk + c + 4];
    }

    float o[8][4];                       // O accum, nb = 0..7 (cols 8nb+2c,+1; rows g,g+8)
#pragma unroll
    for (int nb = 0; nb < 8; nb++)
#pragma unroll
        for (int i = 0; i < 4; i++) o[nb][i] = 0.f;
    float m0 = -INFINITY, m1 = -INFINITY, l0 = 0.f, l1 = 0.f;

    for (int jb = jb_lo; jb < jb_hi; jb++) {
        const float* Kg = g_k + ((size_t)b * TT + (size_t)jb * BN) * HD;
        const float* Vg = g_v + ((size_t)b * TT + (size_t)jb * BN) * HD;

        __syncthreads();   // prior-iter Ks/Vs/Ps reads done (also covers Q-frag reads)
#pragma unroll
        for (int it = 0; it < 4; it++) {
            int f = tid + it * 256;      // 1024 float4s = 64x64
            int row = f >> 4, c4 = (f & 15) << 2;
            float4 kv = *(const float4*)&Kg[(size_t)row * HD + c4];
            *(uint4*)&Ks[row][c4] = make_uint4(f2tf(kv.x), f2tf(kv.y), f2tf(kv.z), f2tf(kv.w));
            float4 vv = *(const float4*)&Vg[(size_t)row * HD + c4];
            *(uint4*)&Vs[row][c4] = make_uint4(f2tf(vv.x), f2tf(vv.y), f2tf(vv.z), f2tf(vv.w));
        }
        __syncthreads();

        // ---- S = Q K^T ----
        float s[8][4];
#pragma unroll
        for (int nb = 0; nb < 8; nb++) {
            s[nb][0] = s[nb][1] = s[nb][2] = s[nb][3] = 0.f;
#pragma unroll
            for (int kk = 0; kk < 8; kk++) {
                uint32_t b0 = Ks[8 * nb + g][8 * kk + c];
                uint32_t b1 = Ks[8 * nb + g][8 * kk + c + 4];
                mma_tf32(s[nb][0], s[nb][1], s[nb][2], s[nb][3],
                         qf[kk][0], qf[kk][1], qf[kk][2], qf[kk][3], b0, b1);
            }
        }

        // ---- causal mask (only needed on the two diagonal tiles) ----
        if (jb >= n_tiles - 2) {
            const int row0g = qb * BM + 16 * w + g;       // global q row (and +8)
            const int col0g = jb * BN + 2 * c;            // + 8*nb (+1)
#pragma unroll
            for (int nb = 0; nb < 8; nb++) {
                int cg = col0g + 8 * nb;
                if (cg     > row0g)     s[nb][0] = -INFINITY;
                if (cg + 1 > row0g)     s[nb][1] = -INFINITY;
                if (cg     > row0g + 8) s[nb][2] = -INFINITY;
                if (cg + 1 > row0g + 8) s[nb][3] = -INFINITY;
            }
        }

        // ---- online softmax (base-2) ----
        float mx0 = -INFINITY, mx1 = -INFINITY;
#pragma unroll
        for (int nb = 0; nb < 8; nb++) {
            mx0 = fmaxf(mx0, fmaxf(s[nb][0], s[nb][1]));
            mx1 = fmaxf(mx1, fmaxf(s[nb][2], s[nb][3]));
        }
#pragma unroll
        for (int off = 1; off <= 2; off <<= 1) {
            mx0 = fmaxf(mx0, __shfl_xor_sync(0xffffffffu, mx0, off));
            mx1 = fmaxf(mx1, __shfl_xor_sync(0xffffffffu, mx1, off));
        }
        float mn0 = fmaxf(m0, mx0), mn1 = fmaxf(m1, mx1);
        float a0 = exp2f(m0 - mn0), a1 = exp2f(m1 - mn1);
        m0 = mn0; m1 = mn1;

        float rs0 = 0.f, rs1 = 0.f;
#pragma unroll
        for (int nb = 0; nb < 8; nb++) {
            float p0 = exp2f(s[nb][0] - m0);
            float p1 = exp2f(s[nb][1] - m0);
            float p2 = exp2f(s[nb][2] - m1);
            float p3 = exp2f(s[nb][3] - m1);
            rs0 += p0 + p1; rs1 += p2 + p3;
            // store P (tf32) to Ps in C-layout
            Ps[16 * w + g][8 * nb + 2 * c]         = f2tf(p0);
            Ps[16 * w + g][8 * nb + 2 * c + 1]     = f2tf(p1);
            Ps[16 * w + g + 8][8 * nb + 2 * c]     = f2tf(p2);
            Ps[16 * w + g + 8][8 * nb + 2 * c + 1] = f2tf(p3);
        }
#pragma unroll
        for (int off = 1; off <= 2; off <<= 1) {
            rs0 += __shfl_xor_sync(0xffffffffu, rs0, off);
            rs1 += __shfl_xor_sync(0xffffffffu, rs1, off);
        }
        l0 = l0 * a0 + rs0;
        l1 = l1 * a1 + rs1;
#pragma unroll
        for (int nb = 0; nb < 8; nb++) {
            o[nb][0] *= a0; o[nb][1] *= a0;
            o[nb][2] *= a1; o[nb][3] *= a1;
        }
        __syncwarp();   // Ps rows are warp-private; warp-level visibility is enough

        // ---- O += P V ----
#pragma unroll
        for (int kk = 0; kk < 8; kk++) {
            uint32_t pa0 = Ps[16 * w + g][8 * kk + c];
            uint32_t pa1 = Ps[16 * w + g + 8][8 * kk + c];
            uint32_t pa2 = Ps[16 * w + g][8 * kk + c + 4];
            uint32_t pa3 = Ps[16 * w + g + 8][8 * kk + c + 4];
#pragma unroll
            for (int nb = 0; nb < 8; nb++) {
                uint32_t b0 = Vs[8 * kk + c][8 * nb + g];
                uint32_t b1 = Vs[8 * kk + c + 4][8 * nb + g];
                mma_tf32(o[nb][0], o[nb][1], o[nb][2], o[nb][3],
                         pa0, pa1, pa2, pa3, b0, b1);
            }
        }
    }

    // ---- write partials ----
    const int p = ((b * QB_PER_B + qb) << 2) + sp;
    float* pacc = g_pacc + (size_t)p * BM * HD;
    const int r0 = 16 * w + g;
#pragma unroll
    for (int nb = 0; nb < 8; nb++) {
        *(float2*)&pacc[(size_t)r0 * HD + 8 * nb + 2 * c]       = make_float2(o[nb][0], o[nb][1]);
        *(float2*)&pacc[(size_t)(r0 + 8) * HD + 8 * nb + 2 * c] = make_float2(o[nb][2], o[nb][3]);
    }
    if (c == 0) {
        g_pm[p * BM + r0] = m0;     g_pm[p * BM + r0 + 8] = m1;
        g_pl[p * BM + r0] = l0;     g_pl[p * BM + r0 + 8] = l1;
    }
}

// ---------------------------------------------------------------------------
// Combine split partials -> output. One CTA per (b, qb): 128 rows x 64 cols.
// ---------------------------------------------------------------------------
__global__ __launch_bounds__(256) void combine_kernel(float* __restrict__ out) {
    __shared__ float wsm[4][BM];
    __shared__ float linv[BM];

    const int bq = blockIdx.x;                 // 0..127
    const int b = bq >> 5;
    const int qb = bq & 31;
    const int nS = qb / 8 + 1;                 // ceil((2qb+2)/16)
    const int tid = threadIdx.x;
    const int pbase = bq << 2;

    if (tid < BM) {
        float M = -INFINITY;
        for (int s = 0; s < nS; s++)
            M = fmaxf(M, g_pm[(pbase + s) * BM + tid]);
        float L = 0.f;
        for (int s = 0; s < nS; s++) {
            float wgt = exp2f(g_pm[(pbase + s) * BM + tid] - M);   // base-2 m
            wsm[s][tid] = wgt;
            L += g_pl[(pbase + s) * BM + tid] * wgt;
        }
        linv[tid] = 1.0f / L;
    }
    __syncthreads();

    float* og = out + ((size_t)b * TT + (size_t)qb * BM) * HD;
#pragma unroll
    for (int e = 0; e < 32; e++) {
        int flat = tid + e * 256;              // 0..8191
        int row = flat >> 6;
        float sum = 0.f;
        for (int s = 0; s < nS; s++)
            sum += g_pacc[(size_t)(pbase + s) * BM * HD + flat] * wsm[s][row];
        og[flat] = sum * linv[row];
    }
}

// ---------------------------------------------------------------------------
extern "C" void kernel_launch(void* const* d_in, const int* in_sizes, int n_in,
                              void* d_out, int out_size) {
    const float* x  = (const float*)d_in[0];
    const float* Wk = (const float*)d_in[1];
    const float* Wq = (const float*)d_in[2];
    const float* Wv = (const float*)d_in[3];
    float* out = (float*)d_out;
    (void)in_sizes; (void)n_in; (void)out_size;

    dim3 pgrid(256, 1, 3);
    proj_kernel<<<pgrid, 256>>>(x, Wk, Wq, Wv);

    const int smem_bytes = (64 + 64 + 128) * PAD * (int)sizeof(uint32_t);  // 69632
    static int attr_set = 0;
    if (!attr_set) {
        cudaFuncSetAttribute(flash_kernel,
                             cudaFuncAttributeMaxDynamicSharedMemorySize,
                             smem_bytes);
        attr_set = 1;
    }
    flash_kernel<<<NITEMS, 256, smem_bytes>>>();

    combine_kernel<<<128, 256>>>(out);
}